// round 2
// baseline (speedup 1.0000x reference)
#include <cuda_runtime.h>
#include <math.h>

#define N_NODES   100000
#define N_EDGES   1600000
#define IN_FEAT   128
#define N_HEADS   8
#define OUT_FEAT  16
#define HF        128          // N_HEADS * OUT_FEAT
#define NEG_SLOPE 0.2f

// ---------------- device scratch (static, no allocations) ----------------
__device__ float d_h    [N_NODES * HF];        // projected features  [N,128]
__device__ float d_q    [N_NODES * N_HEADS];   // query (dst side)    [N,8]
__device__ float d_kk   [N_NODES * N_HEADS];   // key (src side)      [N,8]
__device__ float d_smax [N_NODES * N_HEADS];   // segment max         [N,8]
__device__ float d_den  [N_NODES * N_HEADS];   // segment sum         [N,8]
__device__ float d_ex   [N_EDGES * N_HEADS];   // coeff -> exp        [E,8]
__device__ float d_v    [N_NODES * HF];        // aggregated output   [N,128]

// ---------------- helpers ----------------
__device__ __forceinline__ void atomicMaxF(float* addr, float val) {
    // sign-split trick: works for mixed signs, init must be -inf
    if (val >= 0.0f) atomicMax((int*)addr, __float_as_int(val));
    else             atomicMin((unsigned int*)addr, __float_as_uint(val));
}

// ---------------- K0: init scratch ----------------
__global__ void k_init() {
    int i = blockIdx.x * blockDim.x + threadIdx.x;
    if (i < N_NODES * HF) d_v[i] = 0.0f;
    if (i < N_NODES * N_HEADS) {
        d_smax[i] = -INFINITY;
        d_den[i]  = 0.0f;
    }
}

// ---------------- K1: projection  h = x@Wv + bv ; q = h@Wq+bq ; k = h@Wk+bk
// one block (128 threads) per node
__global__ void k_proj(const float* __restrict__ x,
                       const float* __restrict__ Wv, const float* __restrict__ bv,
                       const float* __restrict__ Wq, const float* __restrict__ bq,
                       const float* __restrict__ Wk, const float* __restrict__ bk) {
    __shared__ float xs[IN_FEAT];
    __shared__ float hs[HF];
    const int n = blockIdx.x;
    const int t = threadIdx.x;

    xs[t] = x[(size_t)n * IN_FEAT + t];
    __syncthreads();

    float acc = bv[t];
#pragma unroll 8
    for (int k = 0; k < IN_FEAT; ++k)
        acc = fmaf(xs[k], __ldg(&Wv[k * HF + t]), acc);

    hs[t] = acc;
    d_h[(size_t)n * HF + t] = acc;
    __syncthreads();

    // 16 threads compute the 8 q-dots and 8 k-dots
    if (t < 2 * N_HEADS) {
        const int head = t & (N_HEADS - 1);
        const bool isQ = (t < N_HEADS);
        const float* W = isQ ? Wq : Wk;
        float s = isQ ? bq[head] : bk[head];
#pragma unroll 8
        for (int j = 0; j < HF; ++j)
            s = fmaf(hs[j], __ldg(&W[j * N_HEADS + head]), s);
        if (isQ) d_q [(size_t)n * N_HEADS + head] = s;
        else     d_kk[(size_t)n * N_HEADS + head] = s;
    }
}

// ---------------- K2: edge coeff + segment max ----------------
__global__ void k_edge_max(const int* __restrict__ src,
                           const int* __restrict__ dst) {
    int i = blockIdx.x * blockDim.x + threadIdx.x;   // over E*H
    if (i >= N_EDGES * N_HEADS) return;
    const int e  = i >> 3;
    const int hd = i & 7;
    const int s  = src[e];
    const int d  = dst[e];
    float val = d_kk[s * N_HEADS + hd] + d_q[d * N_HEADS + hd];
    float coeff = (val >= 0.0f) ? val : NEG_SLOPE * val;
    d_ex[i] = coeff;
    atomicMaxF(&d_smax[d * N_HEADS + hd], coeff);
}

// ---------------- K3: exp + segment sum ----------------
__global__ void k_edge_exp(const int* __restrict__ dst) {
    int i = blockIdx.x * blockDim.x + threadIdx.x;   // over E*H
    if (i >= N_EDGES * N_HEADS) return;
    const int e  = i >> 3;
    const int hd = i & 7;
    const int d  = dst[e];
    float ex = __expf(d_ex[i] - d_smax[d * N_HEADS + hd]);
    d_ex[i] = ex;
    atomicAdd(&d_den[d * N_HEADS + hd], ex);
}

// ---------------- K4: weighted message scatter ----------------
// 256 threads per block -> 2 edges per block, thread handles one of 128 feats
__global__ void k_scatter(const int* __restrict__ src,
                          const int* __restrict__ dst) {
    const int t = threadIdx.x;
    const int e = blockIdx.x * 2 + (t >> 7);
    if (e >= N_EDGES) return;
    const int f  = t & 127;
    const int hd = f >> 4;           // f / OUT_FEAT
    const int s  = src[e];
    const int d  = dst[e];
    const float attn = d_ex[e * N_HEADS + hd] / d_den[d * N_HEADS + hd];
    const float m = d_h[(size_t)s * HF + f] * attn;
    atomicAdd(&d_v[(size_t)d * HF + f], m);
}

// ---------------- K5: mean over heads ----------------
__global__ void k_mean(float* __restrict__ out) {
    int i = blockIdx.x * blockDim.x + threadIdx.x;   // over N*OUT_FEAT
    if (i >= N_NODES * OUT_FEAT) return;
    const int n = i / OUT_FEAT;
    const int f = i - n * OUT_FEAT;
    float s = 0.0f;
#pragma unroll
    for (int hd = 0; hd < N_HEADS; ++hd)
        s += d_v[(size_t)n * HF + hd * OUT_FEAT + f];
    out[i] = s * (1.0f / N_HEADS);
}

// ---------------- launch ----------------
extern "C" void kernel_launch(void* const* d_in, const int* in_sizes, int n_in,
                              void* d_out, int out_size) {
    const float* x   = (const float*)d_in[0];
    const int*   src = (const int*)d_in[1];
    const int*   dst = (const int*)d_in[2];
    const float* Wv  = (const float*)d_in[3];
    const float* bv  = (const float*)d_in[4];
    const float* Wq  = (const float*)d_in[5];
    const float* bq  = (const float*)d_in[6];
    const float* Wk  = (const float*)d_in[7];
    const float* bk  = (const float*)d_in[8];
    float* out = (float*)d_out;

    const int EH = N_EDGES * N_HEADS;

    k_init<<<(N_NODES * HF + 255) / 256, 256>>>();
    k_proj<<<N_NODES, IN_FEAT>>>(x, Wv, bv, Wq, bq, Wk, bk);
    k_edge_max<<<(EH + 255) / 256, 256>>>(src, dst);
    k_edge_exp<<<(EH + 255) / 256, 256>>>(dst);
    k_scatter<<<N_EDGES / 2, 256>>>(src, dst);
    k_mean<<<(N_NODES * OUT_FEAT + 255) / 256, 256>>>(out);
}

// round 3
// speedup vs baseline: 1.5293x; 1.5293x over previous
#include <cuda_runtime.h>
#include <math.h>

#define N_NODES   100000
#define N_EDGES   1600000
#define IN_FEAT   128
#define N_HEADS   8
#define OUT_FEAT  16
#define HF        128
#define NEG_SLOPE 0.2f

// ---------------- device scratch ----------------
__device__ float d_h   [N_NODES * HF];        // projected features  [N,128]
__device__ float d_q   [N_NODES * N_HEADS];   // query (dst side)
__device__ float d_kk  [N_NODES * N_HEADS];   // key   (src side)
__device__ float d_den [N_NODES * N_HEADS];   // sum of exp per (node,head)
__device__ float d_v   [N_NODES * HF];        // unnormalized aggregate

// ---------------- K0: init ----------------
__global__ void k_init() {
    int i = blockIdx.x * blockDim.x + threadIdx.x;
    if (i < N_NODES * HF) d_v[i] = 0.0f;
    if (i < N_NODES * N_HEADS) d_den[i] = 0.0f;
}

// ---------------- K1: tiled GEMM  h = x @ Wv + bv ----------------
// BM=64 nodes, BN=128 (full), BK=16. 256 threads, each computes 8x4 outputs.
#define BM 64
#define BK 16
__global__ __launch_bounds__(256) void k_gemm(const float* __restrict__ x,
                                              const float* __restrict__ Wv,
                                              const float* __restrict__ bv) {
    __shared__ float Xs[BK][BM + 1];   // +1 pad: avoid STS bank conflicts
    __shared__ float Ws[BK][HF];

    const int tid = threadIdx.x;
    const int tx  = tid & 31;          // 0..31 -> feature group (4 feats)
    const int ty  = tid >> 5;          // 0..7  -> node group (8 nodes)
    const int bm  = blockIdx.x * BM;

    float acc[8][4];
#pragma unroll
    for (int m = 0; m < 8; ++m)
#pragma unroll
        for (int j = 0; j < 4; ++j) acc[m][j] = 0.0f;

    for (int k0 = 0; k0 < IN_FEAT; k0 += BK) {
        // load X tile: 64 nodes x 16 k = 1024 elems, 4 per thread
#pragma unroll
        for (int i = 0; i < 4; ++i) {
            int idx = tid + i * 256;
            int nl  = idx >> 4;        // node_local
            int kk  = idx & 15;
            int node = bm + nl;
            float val = (node < N_NODES) ? x[(size_t)node * IN_FEAT + k0 + kk] : 0.0f;
            Xs[kk][nl] = val;
        }
        // load W tile: 16 k x 128 feats = 2048 elems, 8 per thread
#pragma unroll
        for (int i = 0; i < 8; ++i) {
            int idx = tid + i * 256;
            int kk  = idx >> 7;
            int f   = idx & 127;
            Ws[kk][f] = Wv[(size_t)(k0 + kk) * HF + f];
        }
        __syncthreads();

#pragma unroll
        for (int kk = 0; kk < BK; ++kk) {
            float4 w = *(const float4*)&Ws[kk][tx * 4];
            float xm[8];
#pragma unroll
            for (int m = 0; m < 8; ++m) xm[m] = Xs[kk][ty * 8 + m];
#pragma unroll
            for (int m = 0; m < 8; ++m) {
                acc[m][0] = fmaf(xm[m], w.x, acc[m][0]);
                acc[m][1] = fmaf(xm[m], w.y, acc[m][1]);
                acc[m][2] = fmaf(xm[m], w.z, acc[m][2]);
                acc[m][3] = fmaf(xm[m], w.w, acc[m][3]);
            }
        }
        __syncthreads();
    }

    float4 bias = *(const float4*)&bv[tx * 4];
#pragma unroll
    for (int m = 0; m < 8; ++m) {
        int node = bm + ty * 8 + m;
        if (node < N_NODES) {
            float4 r;
            r.x = acc[m][0] + bias.x;
            r.y = acc[m][1] + bias.y;
            r.z = acc[m][2] + bias.z;
            r.w = acc[m][3] + bias.w;
            *(float4*)&d_h[(size_t)node * HF + tx * 4] = r;
        }
    }
}

// ---------------- K2: q/k projections  (8 nodes per 128-thread block) ----
__global__ __launch_bounds__(128) void k_qk(const float* __restrict__ Wq,
                                            const float* __restrict__ bq,
                                            const float* __restrict__ Wk,
                                            const float* __restrict__ bk) {
    __shared__ float hs[8][HF];
    __shared__ float Wqs[HF * N_HEADS];
    __shared__ float Wks[HF * N_HEADS];

    const int t = threadIdx.x;
    const int nb = blockIdx.x * 8;

    // load weights (1024 each, 8 per thread)
#pragma unroll
    for (int i = 0; i < 8; ++i) {
        int idx = t + i * 128;
        Wqs[idx] = Wq[idx];
        Wks[idx] = Wk[idx];
    }
    // load 8 h rows
#pragma unroll
    for (int i = 0; i < 8; ++i) {
        int idx = t + i * 128;
        int nl = idx >> 7;
        int j  = idx & 127;
        int node = nb + nl;
        hs[nl][j] = (node < N_NODES) ? d_h[(size_t)node * HF + j] : 0.0f;
    }
    __syncthreads();

    const int nl  = t >> 4;
    const int id  = t & 15;
    const int hd  = id & 7;
    const bool isQ = (id < 8);
    const int node = nb + nl;
    if (node >= N_NODES) return;

    const float* W = isQ ? Wqs : Wks;
    float s = isQ ? bq[hd] : bk[hd];
#pragma unroll 16
    for (int j = 0; j < HF; ++j)
        s = fmaf(hs[nl][j], W[j * N_HEADS + hd], s);

    if (isQ) d_q [node * N_HEADS + hd] = s;
    else     d_kk[node * N_HEADS + hd] = s;
}

// ---------------- K3: fused edge pass ----------------
// softmax shift-invariance: exp(coeff) directly (coeff bounded ~|8|, safe in fp32)
// per edge: ex[hd] = exp(leaky(k[src]+q[dst])); den[dst,hd]+=ex; v[dst,f]+=ex*h[src,f]
__global__ __launch_bounds__(256) void k_edge(const int* __restrict__ src,
                                              const int* __restrict__ dst) {
    const int t = threadIdx.x;
    const int e = blockIdx.x * 2 + (t >> 7);
    if (e >= N_EDGES) return;
    const int f  = t & 127;
    const int hd = f >> 4;
    const int s  = src[e];
    const int d  = dst[e];

    float coeff = d_kk[s * N_HEADS + hd] + d_q[d * N_HEADS + hd];
    coeff = (coeff >= 0.0f) ? coeff : NEG_SLOPE * coeff;
    const float ex = __expf(coeff);

    const float m = ex * d_h[(size_t)s * HF + f];
    atomicAdd(&d_v[(size_t)d * HF + f], m);
    if ((f & 15) == 0) atomicAdd(&d_den[d * N_HEADS + hd], ex);
}

// ---------------- K4: normalize + head mean ----------------
__global__ void k_mean(float* __restrict__ out) {
    int i = blockIdx.x * blockDim.x + threadIdx.x;   // over N*OUT_FEAT
    if (i >= N_NODES * OUT_FEAT) return;
    const int n = i >> 4;
    const int f = i & 15;
    float s = 0.0f;
#pragma unroll
    for (int hd = 0; hd < N_HEADS; ++hd) {
        float den = d_den[n * N_HEADS + hd];
        float v   = d_v[(size_t)n * HF + hd * OUT_FEAT + f];
        s += (den > 0.0f) ? v / den : 0.0f;
    }
    out[i] = s * (1.0f / N_HEADS);
}

// ---------------- launch ----------------
extern "C" void kernel_launch(void* const* d_in, const int* in_sizes, int n_in,
                              void* d_out, int out_size) {
    const float* x   = (const float*)d_in[0];
    const int*   src = (const int*)d_in[1];
    const int*   dst = (const int*)d_in[2];
    const float* Wv  = (const float*)d_in[3];
    const float* bv  = (const float*)d_in[4];
    const float* Wq  = (const float*)d_in[5];
    const float* bq  = (const float*)d_in[6];
    const float* Wk  = (const float*)d_in[7];
    const float* bk  = (const float*)d_in[8];
    float* out = (float*)d_out;

    k_init<<<(N_NODES * HF + 255) / 256, 256>>>();
    k_gemm<<<(N_NODES + BM - 1) / BM, 256>>>(x, Wv, bv);
    k_qk<<<(N_NODES + 7) / 8, 128>>>(Wq, bq, Wk, bk);
    k_edge<<<N_EDGES / 2, 256>>>(src, dst);
    k_mean<<<(N_NODES * OUT_FEAT + 255) / 256, 256>>>(out);
}

// round 4
// speedup vs baseline: 5.5490x; 3.6284x over previous
#include <cuda_runtime.h>
#include <math.h>

#define N_NODES   100000
#define N_EDGES   1600000
#define IN_FEAT   128
#define N_HEADS   8
#define OUT_FEAT  16
#define HF        128
#define NEG_SLOPE 0.2f

#define SCAN_B    512
#define NB1       ((N_NODES + SCAN_B - 1) / SCAN_B)   // 196

// ---------------- device scratch ----------------
__device__ float d_h   [N_NODES * HF];        // projected features
__device__ float d_q   [N_NODES * N_HEADS];
__device__ float d_kk  [N_NODES * N_HEADS];
__device__ int   d_deg [N_NODES];
__device__ int   d_off [N_NODES];             // exclusive scan of deg
__device__ int   d_pos [N_NODES];             // fill cursor
__device__ int   d_csrc[N_EDGES];             // src ids sorted by dst
__device__ int   d_bsum[NB1];
__device__ int   d_bsum2[NB1];

// ---------------- K0: init ----------------
__global__ void k_init() {
    int i = blockIdx.x * blockDim.x + threadIdx.x;
    if (i < N_NODES) d_deg[i] = 0;
}

// ---------------- K1: tiled GEMM  h = x @ Wv + bv ----------------
#define BM 64
#define BK 16
__global__ __launch_bounds__(256) void k_gemm(const float* __restrict__ x,
                                              const float* __restrict__ Wv,
                                              const float* __restrict__ bv) {
    __shared__ float Xs[BK][BM + 1];
    __shared__ float Ws[BK][HF];

    const int tid = threadIdx.x;
    const int tx  = tid & 31;
    const int ty  = tid >> 5;
    const int bm  = blockIdx.x * BM;

    float acc[8][4];
#pragma unroll
    for (int m = 0; m < 8; ++m)
#pragma unroll
        for (int j = 0; j < 4; ++j) acc[m][j] = 0.0f;

    for (int k0 = 0; k0 < IN_FEAT; k0 += BK) {
#pragma unroll
        for (int i = 0; i < 4; ++i) {
            int idx = tid + i * 256;
            int nl  = idx >> 4;
            int kk  = idx & 15;
            int node = bm + nl;
            Xs[kk][nl] = (node < N_NODES) ? x[(size_t)node * IN_FEAT + k0 + kk] : 0.0f;
        }
#pragma unroll
        for (int i = 0; i < 8; ++i) {
            int idx = tid + i * 256;
            int kk  = idx >> 7;
            int f   = idx & 127;
            Ws[kk][f] = Wv[(size_t)(k0 + kk) * HF + f];
        }
        __syncthreads();

#pragma unroll
        for (int kk = 0; kk < BK; ++kk) {
            float4 w = *(const float4*)&Ws[kk][tx * 4];
            float xm[8];
#pragma unroll
            for (int m = 0; m < 8; ++m) xm[m] = Xs[kk][ty * 8 + m];
#pragma unroll
            for (int m = 0; m < 8; ++m) {
                acc[m][0] = fmaf(xm[m], w.x, acc[m][0]);
                acc[m][1] = fmaf(xm[m], w.y, acc[m][1]);
                acc[m][2] = fmaf(xm[m], w.z, acc[m][2]);
                acc[m][3] = fmaf(xm[m], w.w, acc[m][3]);
            }
        }
        __syncthreads();
    }

    float4 bias = *(const float4*)&bv[tx * 4];
#pragma unroll
    for (int m = 0; m < 8; ++m) {
        int node = bm + ty * 8 + m;
        if (node < N_NODES) {
            float4 r;
            r.x = acc[m][0] + bias.x;
            r.y = acc[m][1] + bias.y;
            r.z = acc[m][2] + bias.z;
            r.w = acc[m][3] + bias.w;
            *(float4*)&d_h[(size_t)node * HF + tx * 4] = r;
        }
    }
}

// ---------------- K2: q/k projections ----------------
__global__ __launch_bounds__(128) void k_qk(const float* __restrict__ Wq,
                                            const float* __restrict__ bq,
                                            const float* __restrict__ Wk,
                                            const float* __restrict__ bk) {
    __shared__ float hs[8][HF];
    __shared__ float Wqs[HF * N_HEADS];
    __shared__ float Wks[HF * N_HEADS];

    const int t = threadIdx.x;
    const int nb = blockIdx.x * 8;

#pragma unroll
    for (int i = 0; i < 8; ++i) {
        int idx = t + i * 128;
        Wqs[idx] = Wq[idx];
        Wks[idx] = Wk[idx];
    }
#pragma unroll
    for (int i = 0; i < 8; ++i) {
        int idx = t + i * 128;
        int nl = idx >> 7;
        int j  = idx & 127;
        int node = nb + nl;
        hs[nl][j] = (node < N_NODES) ? d_h[(size_t)node * HF + j] : 0.0f;
    }
    __syncthreads();

    const int nl  = t >> 4;
    const int id  = t & 15;
    const int hd  = id & 7;
    const bool isQ = (id < 8);
    const int node = nb + nl;
    if (node >= N_NODES) return;

    const float* W = isQ ? Wqs : Wks;
    float s = isQ ? bq[hd] : bk[hd];
#pragma unroll 16
    for (int j = 0; j < HF; ++j)
        s = fmaf(hs[nl][j], W[j * N_HEADS + hd], s);

    if (isQ) d_q [node * N_HEADS + hd] = s;
    else     d_kk[node * N_HEADS + hd] = s;
}

// ---------------- CSR build ----------------
__global__ void k_count(const int* __restrict__ dst) {
    int e = blockIdx.x * blockDim.x + threadIdx.x;
    if (e < N_EDGES) atomicAdd(&d_deg[dst[e]], 1);
}

__global__ __launch_bounds__(SCAN_B) void k_scan1() {
    __shared__ int tmp[2][SCAN_B];
    const int t = threadIdx.x;
    const int i = blockIdx.x * SCAN_B + t;
    int v = (i < N_NODES) ? d_deg[i] : 0;
    tmp[0][t] = v;
    __syncthreads();
    int pp = 0;
    for (int off = 1; off < SCAN_B; off <<= 1) {
        int x = tmp[pp][t];
        if (t >= off) x += tmp[pp][t - off];
        tmp[pp ^ 1][t] = x;
        pp ^= 1;
        __syncthreads();
    }
    int incl = tmp[pp][t];
    if (i < N_NODES) d_off[i] = incl - v;
    if (t == SCAN_B - 1) d_bsum[blockIdx.x] = incl;
}

__global__ __launch_bounds__(256) void k_scan2() {
    __shared__ int tmp[2][256];
    const int t = threadIdx.x;
    int v = (t < NB1) ? d_bsum[t] : 0;
    tmp[0][t] = v;
    __syncthreads();
    int pp = 0;
    for (int off = 1; off < 256; off <<= 1) {
        int x = tmp[pp][t];
        if (t >= off) x += tmp[pp][t - off];
        tmp[pp ^ 1][t] = x;
        pp ^= 1;
        __syncthreads();
    }
    if (t < NB1) d_bsum2[t] = tmp[pp][t] - v;   // exclusive
}

__global__ __launch_bounds__(SCAN_B) void k_scan3() {
    const int i = blockIdx.x * SCAN_B + threadIdx.x;
    if (i < N_NODES) {
        int o = d_off[i] + d_bsum2[blockIdx.x];
        d_off[i] = o;
        d_pos[i] = o;
    }
}

__global__ void k_fill(const int* __restrict__ src, const int* __restrict__ dst) {
    int e = blockIdx.x * blockDim.x + threadIdx.x;
    if (e >= N_EDGES) return;
    int p = atomicAdd(&d_pos[dst[e]], 1);
    d_csrc[p] = src[e];
}

// ---------------- K3: fused softmax + aggregate + normalize + head-mean ----
// one warp per dst node; lane l covers feats [4l, 4l+4), head = l>>2
__global__ __launch_bounds__(128) void k_agg(float* __restrict__ out) {
    const int n = blockIdx.x * 4 + (threadIdx.x >> 5);
    if (n >= N_NODES) return;
    const int l  = threadIdx.x & 31;
    const int hd = l >> 2;

    const float qv    = d_q[n * N_HEADS + hd];
    const int   start = d_off[n];
    const int   deg   = d_deg[n];

    float4 acc = make_float4(0.f, 0.f, 0.f, 0.f);
    float  den = 0.f;

    int j = 0;
    for (; j + 1 < deg; j += 2) {
        const int s0 = d_csrc[start + j];
        const int s1 = d_csrc[start + j + 1];
        const float kk0 = d_kk[s0 * N_HEADS + hd];
        const float kk1 = d_kk[s1 * N_HEADS + hd];
        const float4 h0 = *(const float4*)&d_h[(size_t)s0 * HF + l * 4];
        const float4 h1 = *(const float4*)&d_h[(size_t)s1 * HF + l * 4];
        float c0 = kk0 + qv; c0 = (c0 >= 0.f) ? c0 : NEG_SLOPE * c0;
        float c1 = kk1 + qv; c1 = (c1 >= 0.f) ? c1 : NEG_SLOPE * c1;
        const float e0 = __expf(c0);
        const float e1 = __expf(c1);
        acc.x = fmaf(e0, h0.x, acc.x); acc.y = fmaf(e0, h0.y, acc.y);
        acc.z = fmaf(e0, h0.z, acc.z); acc.w = fmaf(e0, h0.w, acc.w);
        acc.x = fmaf(e1, h1.x, acc.x); acc.y = fmaf(e1, h1.y, acc.y);
        acc.z = fmaf(e1, h1.z, acc.z); acc.w = fmaf(e1, h1.w, acc.w);
        den += e0 + e1;
    }
    if (j < deg) {
        const int s0 = d_csrc[start + j];
        const float kk0 = d_kk[s0 * N_HEADS + hd];
        const float4 h0 = *(const float4*)&d_h[(size_t)s0 * HF + l * 4];
        float c0 = kk0 + qv; c0 = (c0 >= 0.f) ? c0 : NEG_SLOPE * c0;
        const float e0 = __expf(c0);
        acc.x = fmaf(e0, h0.x, acc.x); acc.y = fmaf(e0, h0.y, acc.y);
        acc.z = fmaf(e0, h0.z, acc.z); acc.w = fmaf(e0, h0.w, acc.w);
        den += e0;
    }

    const float inv = (deg > 0) ? 1.0f / den : 0.0f;
    acc.x *= inv; acc.y *= inv; acc.z *= inv; acc.w *= inv;

    // head mean: sum lanes with equal l%4 (strides 4, 8, 16)
#pragma unroll
    for (int off = 4; off < 32; off <<= 1) {
        acc.x += __shfl_xor_sync(0xffffffff, acc.x, off);
        acc.y += __shfl_xor_sync(0xffffffff, acc.y, off);
        acc.z += __shfl_xor_sync(0xffffffff, acc.z, off);
        acc.w += __shfl_xor_sync(0xffffffff, acc.w, off);
    }

    if (l < 4) {
        float4 r;
        r.x = acc.x * (1.0f / N_HEADS);
        r.y = acc.y * (1.0f / N_HEADS);
        r.z = acc.z * (1.0f / N_HEADS);
        r.w = acc.w * (1.0f / N_HEADS);
        *(float4*)&out[(size_t)n * OUT_FEAT + l * 4] = r;
    }
}

// ---------------- launch ----------------
extern "C" void kernel_launch(void* const* d_in, const int* in_sizes, int n_in,
                              void* d_out, int out_size) {
    const float* x   = (const float*)d_in[0];
    const int*   src = (const int*)d_in[1];
    const int*   dst = (const int*)d_in[2];
    const float* Wv  = (const float*)d_in[3];
    const float* bv  = (const float*)d_in[4];
    const float* Wq  = (const float*)d_in[5];
    const float* bq  = (const float*)d_in[6];
    const float* Wk  = (const float*)d_in[7];
    const float* bk  = (const float*)d_in[8];
    float* out = (float*)d_out;

    k_init <<<(N_NODES + 255) / 256, 256>>>();
    k_gemm <<<(N_NODES + BM - 1) / BM, 256>>>(x, Wv, bv);
    k_qk   <<<(N_NODES + 7) / 8, 128>>>(Wq, bq, Wk, bk);
    k_count<<<(N_EDGES + 255) / 256, 256>>>(dst);
    k_scan1<<<NB1, SCAN_B>>>();
    k_scan2<<<1, 256>>>();
    k_scan3<<<NB1, SCAN_B>>>();
    k_fill <<<(N_EDGES + 255) / 256, 256>>>(src, dst);
    k_agg  <<<(N_NODES + 3) / 4, 128>>>(out);
}